// round 4
// baseline (speedup 1.0000x reference)
#include <cuda_runtime.h>
#include <cstdint>

#define TPB    256
#define TROWS  512                  // rows per tile (2 per thread)
#define TILE_F (TROWS * 10)         // 5120 floats = 20480 B per buffer

__global__ void __launch_bounds__(TPB) encoder_kernel(
    const float* __restrict__ x,   // [N,10]
    const float* __restrict__ t,   // [N,1]
    const float* __restrict__ y,   // [N,1]
    const float* __restrict__ w,   // [2048]
    const float* __restrict__ b,   // [2048]
    float* __restrict__ out,       // [N,1]
    int n)
{
    __shared__ float sx[2][TILE_F];

    const int ntiles = (n + TROWS - 1) / TROWS;
    int tile = blockIdx.x;
    if (tile >= ntiles) return;

    const int tid = threadIdx.x;

    // ---- stage helper (inlined twice): cooperative coalesced cp.async ----
    auto stage = [&](int tl, int buf) {
        const int rows = min(TROWS, n - tl * TROWS);
        const int nf   = rows * 10;
        const int nf4  = nf >> 2;
        const float* src = x + (size_t)tl * TILE_F;
        uint32_t dbase = (uint32_t)__cvta_generic_to_shared(&sx[buf][0]);
        #pragma unroll 5
        for (int k = tid; k < nf4; k += TPB) {
            asm volatile("cp.async.cg.shared.global [%0], [%1], 16;\n"
                         :: "r"(dbase + k * 16), "l"((const float4*)src + k));
        }
        for (int k = (nf4 << 2) + tid; k < nf; k += TPB)   // generic-n tail
            sx[buf][k] = src[k];
    };

    // prologue: stage first tile
    stage(tile, 0);
    asm volatile("cp.async.commit_group;\n");
    int buf = 0;

    while (true) {
        const int next = tile + gridDim.x;
        const bool have_next = (next < ntiles);

        // prefetch next tile into other buffer BEFORE waiting on current
        if (have_next) {
            stage(next, buf ^ 1);
            asm volatile("cp.async.commit_group;\n");
        }

        // early-issue t/y for this thread's row pair (overlaps with waits)
        const int i0 = tile * TROWS + 2 * tid;
        float2 tv = make_float2(0.f, 0.f), yv = make_float2(0.f, 0.f);
        const bool full_pair = (i0 + 1 < n);
        if (full_pair) {
            tv = *(const float2*)(t + i0);
            yv = *(const float2*)(y + i0);
        } else if (i0 < n) {
            tv.x = t[i0];
            yv.x = y[i0];
        }

        if (have_next) { asm volatile("cp.async.wait_group 1;\n" ::: "memory"); }
        else           { asm volatile("cp.async.wait_group 0;\n" ::: "memory"); }
        __syncthreads();

        if (i0 < n) {
            // 5 x LDS.128 (word offset 20*tid: conflict-free phase pattern)
            const float* xr = &sx[buf][2 * tid * 10];
            int idx0 = 0, idx1 = 0;
            #pragma unroll
            for (int q = 0; q < 5; ++q) {
                float4 f = *(const float4*)(xr + q * 4);
                float e[4] = {f.x, f.y, f.z, f.w};
                #pragma unroll
                for (int c = 0; c < 4; ++c) {
                    int fi = 4 * q + c;
                    int bit = (e[c] != 0.0f) ? 1 : 0;
                    if (fi < 10) idx0 = (idx0 << 1) | bit;
                    else         idx1 = (idx1 << 1) | bit;
                }
            }
            idx0 |= ((tv.x != 0.0f) ? 1 : 0) << 10;
            idx1 |= ((tv.y != 0.0f) ? 1 : 0) << 10;

            float w0 = __ldg(w + idx0), b0 = __ldg(b + idx0);
            if (full_pair) {
                float w1 = __ldg(w + idx1), b1 = __ldg(b + idx1);
                float2 o;
                o.x = fmaf(yv.x, w0, b0);
                o.y = fmaf(yv.y, w1, b1);
                *(float2*)(out + i0) = o;
            } else {
                out[i0] = fmaf(yv.x, w0, b0);
            }
        }

        tile = next;
        buf ^= 1;
        if (!have_next) break;
        __syncthreads();   // all reads of old buffer done before next stage overwrites it
    }
}

extern "C" void kernel_launch(void* const* d_in, const int* in_sizes, int n_in,
                              void* d_out, int out_size)
{
    const float* x = (const float*)d_in[0];
    const float* t = (const float*)d_in[1];
    const float* y = (const float*)d_in[2];
    const float* w = (const float*)d_in[3];
    const float* b = (const float*)d_in[4];
    float* out = (float*)d_out;

    int n = in_sizes[1];
    int ntiles = (n + TROWS - 1) / TROWS;
    int blocks = 5 * 152;               // 5 CTAs/SM x 152 SMs (GB300)
    if (blocks > ntiles) blocks = ntiles;
    encoder_kernel<<<blocks, TPB>>>(x, t, y, w, b, out, n);
}

// round 5
// speedup vs baseline: 1.2092x; 1.2092x over previous
#include <cuda_runtime.h>
#include <cstdint>

#define TPB   256
#define WARPS (TPB / 32)

__global__ void __launch_bounds__(TPB) encoder_ballot_kernel(
    const float* __restrict__ x,   // [N,10]
    const float* __restrict__ t,   // [N,1]
    const float* __restrict__ y,   // [N,1]
    const float* __restrict__ w,   // [2048]
    const float* __restrict__ b,   // [2048]
    float* __restrict__ out,       // [N,1]
    int n)
{
    __shared__ uint32_t sw[WARPS][12];   // 10 ballot words + pad

    const int warp = threadIdx.x >> 5;
    const int lane = threadIdx.x & 31;
    const int wrow = (blockIdx.x * WARPS + warp) * 32;  // first row of this warp
    if (wrow >= n) return;

    // valid float count in this warp's 320-float slab (tail safety)
    const int limit = n * 10 - wrow * 10;
    const float* xs = x + (size_t)wrow * 10;

    // zero the pad word (read by funnelshift for lanes 29-31, contributes nothing)
    if (lane == 0) sw[warp][10] = 0u;

    // ---- 10 coalesced loads -> 10 ballots; word q holds bits of floats [32q,32q+32) ----
#pragma unroll
    for (int q = 0; q < 10; ++q) {
        const int off = q * 32 + lane;
        float v = (off < limit) ? __ldg(xs + off) : 0.0f;
        uint32_t bq = __ballot_sync(0xffffffffu, v != 0.0f);
        if (lane == q) sw[warp][q] = bq;
    }

    // ---- coalesced t/y for this lane's row ----
    const int i = wrow + lane;
    float tv = 0.0f, yv = 0.0f;
    if (i < n) { tv = __ldg(t + i); yv = __ldg(y + i); }

    __syncwarp();

    // ---- extract this row's 10-bit field from the 320-bit ballot stream ----
    const int start = 10 * lane;                 // bit offset of row's bits
    const int widx  = start >> 5;
    const uint32_t lo = sw[warp][widx];
    const uint32_t hi = sw[warp][widx + 1];
    uint32_t field = __funnelshift_r(lo, hi, start & 31) & 0x3FFu;
    // field bit c = x_c (weight 2^(9-c)) -> reverse the 10-bit field
    int idx = (int)(__brev(field) >> 22);
    idx |= ((tv != 0.0f) ? 1 : 0) << 10;

    if (i < n)
        out[i] = fmaf(yv, __ldg(w + idx), __ldg(b + idx));
}

extern "C" void kernel_launch(void* const* d_in, const int* in_sizes, int n_in,
                              void* d_out, int out_size)
{
    const float* x = (const float*)d_in[0];
    const float* t = (const float*)d_in[1];
    const float* y = (const float*)d_in[2];
    const float* w = (const float*)d_in[3];
    const float* b = (const float*)d_in[4];
    float* out = (float*)d_out;

    int n = in_sizes[1];
    int blocks = (n + TPB - 1) / TPB;
    encoder_ballot_kernel<<<blocks, TPB>>>(x, t, y, w, b, out, n);
}

// round 6
// speedup vs baseline: 1.3333x; 1.1027x over previous
#include <cuda_runtime.h>
#include <cstdint>

#define TPB 256

__global__ void __launch_bounds__(TPB) encoder_direct_kernel(
    const float* __restrict__ x,   // [N,10]
    const float* __restrict__ t,   // [N,1]
    const float* __restrict__ y,   // [N,1]
    const float* __restrict__ w,   // [2048]
    const float* __restrict__ b,   // [2048]
    float* __restrict__ out,       // [N,1]
    int n)
{
    const int tid = blockIdx.x * TPB + threadIdx.x;
    const int i0  = tid * 2;                   // first of 2 rows
    if (i0 >= n) return;

    if (i0 + 1 < n) {
        // ---- fast path: 2 full rows = 80B = 5 aligned LDG.128, front-batched ----
        const float4* xv = (const float4*)(x + (size_t)i0 * 10);
        float4 f0 = __ldg(xv + 0);
        float4 f1 = __ldg(xv + 1);
        float4 f2 = __ldg(xv + 2);
        float4 f3 = __ldg(xv + 3);
        float4 f4 = __ldg(xv + 4);
        float2 tv = __ldg((const float2*)(t + i0));   // i0 even -> 8B aligned
        float2 yv = __ldg((const float2*)(y + i0));

        // row0 bits: f0.xyzw f1.xyzw f2.xy  (MSB first: x0 -> 2^9)
        int idx0 =
            ((f0.x != 0.f) << 9) | ((f0.y != 0.f) << 8) |
            ((f0.z != 0.f) << 7) | ((f0.w != 0.f) << 6) |
            ((f1.x != 0.f) << 5) | ((f1.y != 0.f) << 4) |
            ((f1.z != 0.f) << 3) | ((f1.w != 0.f) << 2) |
            ((f2.x != 0.f) << 1) | ((f2.y != 0.f) << 0) |
            ((tv.x != 0.f) << 10);
        // row1 bits: f2.zw f3.xyzw f4.xyzw
        int idx1 =
            ((f2.z != 0.f) << 9) | ((f2.w != 0.f) << 8) |
            ((f3.x != 0.f) << 7) | ((f3.y != 0.f) << 6) |
            ((f3.z != 0.f) << 5) | ((f3.w != 0.f) << 4) |
            ((f4.x != 0.f) << 3) | ((f4.y != 0.f) << 2) |
            ((f4.z != 0.f) << 1) | ((f4.w != 0.f) << 0) |
            ((tv.y != 0.f) << 10);

        float2 o;
        o.x = fmaf(yv.x, __ldg(w + idx0), __ldg(b + idx0));
        o.y = fmaf(yv.y, __ldg(w + idx1), __ldg(b + idx1));
        *(float2*)(out + i0) = o;
    } else {
        // ---- tail: single last row, scalar loads ----
        const float* xr = x + (size_t)i0 * 10;
        int idx = 0;
#pragma unroll
        for (int j = 0; j < 10; ++j)
            idx = (idx << 1) | (xr[j] != 0.f ? 1 : 0);
        idx |= (t[i0] != 0.f ? 1 : 0) << 10;
        out[i0] = fmaf(y[i0], __ldg(w + idx), __ldg(b + idx));
    }
}

extern "C" void kernel_launch(void* const* d_in, const int* in_sizes, int n_in,
                              void* d_out, int out_size)
{
    const float* x = (const float*)d_in[0];
    const float* t = (const float*)d_in[1];
    const float* y = (const float*)d_in[2];
    const float* w = (const float*)d_in[3];
    const float* b = (const float*)d_in[4];
    float* out = (float*)d_out;

    int n = in_sizes[1];
    int nthreads = (n + 1) / 2;
    int blocks = (nthreads + TPB - 1) / TPB;
    encoder_direct_kernel<<<blocks, TPB>>>(x, t, y, w, b, out, n);
}